// round 2
// baseline (speedup 1.0000x reference)
#include <cuda_runtime.h>

// NotearsRKHS on GB300.
// out[i,j] = sum_l K[j,i,l] * ( alpha[j,l] + 2*sum_{a!=j} beta[j,a,l]*diff[i,l,a] )
// K[j,i,l] = exp(diff[i,l,j]^2 - S[i,l]),  S = full squared distance, GAMMA=1.
// x:[N,D] f32, alpha:[D,N] f32, beta:[D,D,N] f32, out:[N,D] f32.
//
// Strategy: never materialize K. Per (i,l): 24 packed diffs, packed S, then a
// 24x24 matvec in fp32x2 (Blackwell FFMA2, PTX-only). Each thread handles 2
// i-rows (IPT=2) so every beta row read from smem serves 2 outputs.
// Grid 8 x 36 = 288 CTAs = one wave at occupancy 2. Deterministic split-l
// reduction through a __device__ partial buffer (no float atomics, no allocs).

#define NN 2000
#define DD 24
#define BLK 128
#define IPT 2
#define IBLK (BLK * IPT)      // 256 i per CTA
#define NIB 8                 // ceil(2000/256)
#define LSPLIT 36             // l-chunks across grid.y
#define CHUNK 56              // l per chunk (36*56 = 2016 >= 2000, tail zero-padded)
#define TL 14                 // l-tile in shared
#define NTILES 4              // 56/14
#define BROW 580              // padded beta_s row stride (floats), 16B-multiple

__device__ float g_partial[LSPLIT * NN * DD];

typedef unsigned long long u64;

__device__ __forceinline__ u64 pack2(float lo, float hi) {
    u64 r; asm("mov.b64 %0, {%1,%2};" : "=l"(r) : "f"(lo), "f"(hi)); return r;
}
__device__ __forceinline__ void unpack2(u64 v, float& lo, float& hi) {
    asm("mov.b64 {%0,%1}, %2;" : "=f"(lo), "=f"(hi) : "l"(v));
}
__device__ __forceinline__ u64 ffma2(u64 a, u64 b, u64 c) {
    u64 d; asm("fma.rn.f32x2 %0, %1, %2, %3;" : "=l"(d) : "l"(a), "l"(b), "l"(c)); return d;
}
__device__ __forceinline__ u64 add2(u64 a, u64 b) {
    u64 d; asm("add.rn.f32x2 %0, %1, %2;" : "=l"(d) : "l"(a), "l"(b)); return d;
}

__global__ __launch_bounds__(BLK)
void notears_main(const float* __restrict__ x,
                  const float* __restrict__ alpha,
                  const float* __restrict__ beta)
{
    __shared__ __align__(16) float beta_s[TL * BROW];  // [lt][j*24+a], row 16B-aligned
    __shared__ __align__(16) float nxl_s[TL * 24];     // negated x[l] tile
    __shared__ __align__(16) float al_s[TL * 24];      // alpha[j,l] tile, [lt][j]

    const int tid = threadIdx.x;
    const int i0 = blockIdx.x * IBLK + tid;
    const int i1 = i0 + BLK;
    const int l_base = blockIdx.y * CHUNK;

    // per-thread x rows, packed (zeros for tail threads -> harmless)
    u64 xi2[IPT][12];
    {
        float t0, t1;
        #pragma unroll
        for (int p = 0; p < 12; p++) {
            t0 = (i0 < NN) ? x[i0 * DD + 2*p]     : 0.0f;
            t1 = (i0 < NN) ? x[i0 * DD + 2*p + 1] : 0.0f;
            xi2[0][p] = pack2(t0, t1);
            t0 = (i1 < NN) ? x[i1 * DD + 2*p]     : 0.0f;
            t1 = (i1 < NN) ? x[i1 * DD + 2*p + 1] : 0.0f;
            xi2[1][p] = pack2(t0, t1);
        }
    }

    float acc[IPT][DD];
    #pragma unroll
    for (int r = 0; r < IPT; r++)
        #pragma unroll
        for (int j = 0; j < DD; j++) acc[r][j] = 0.0f;

    for (int tile = 0; tile < NTILES; tile++) {
        const int l0 = l_base + tile * TL;
        __syncthreads();
        // beta tile: beta_s[lt*BROW + ja] = beta[ja*NN + l], zero-pad l >= NN.
        // float2 over lt pairs (l0 even, NN even -> 8B aligned).
        for (int idx = tid; idx < 576 * (TL / 2); idx += BLK) {
            int ja = idx / (TL / 2);
            int p  = idx - ja * (TL / 2);
            int lt = 2 * p;
            int l  = l0 + lt;
            float2 v;
            if (l + 2 <= NN) {
                v = *(const float2*)(beta + (size_t)ja * NN + l);
            } else {
                v.x = (l     < NN) ? beta[(size_t)ja * NN + l]     : 0.0f;
                v.y = (l + 1 < NN) ? beta[(size_t)ja * NN + l + 1] : 0.0f;
            }
            beta_s[lt * BROW + ja]       = v.x;
            beta_s[(lt + 1) * BROW + ja] = v.y;
        }
        // negated x tile
        for (int idx = tid; idx < TL * 24; idx += BLK) {
            int lt = idx / 24;
            int k  = idx - lt * 24;
            int l  = l0 + lt;
            nxl_s[idx] = (l < NN) ? -x[l * DD + k] : 0.0f;
        }
        // alpha tile (zero-pad -> padded l contributes exactly 0)
        for (int idx = tid; idx < TL * 24; idx += BLK) {
            int lt = idx / 24;
            int j  = idx - lt * 24;
            int l  = l0 + lt;
            al_s[lt * 24 + j] = (l < NN) ? alpha[(size_t)j * NN + l] : 0.0f;
        }
        __syncthreads();

        #pragma unroll 1
        for (int lt = 0; lt < TL; lt++) {
            const u64* nxl2 = (const u64*)&nxl_s[lt * 24];

            // packed diffs + squared distance S per i-row
            u64 df2[IPT][12];
            float S[IPT];
            #pragma unroll
            for (int r = 0; r < IPT; r++) {
                u64 sa = 0ull, sb = 0ull;
                #pragma unroll
                for (int p = 0; p < 12; p++) {
                    u64 d = add2(xi2[r][p], nxl2[p]);
                    df2[r][p] = d;
                    if (p & 1) sb = ffma2(d, d, sb); else sa = ffma2(d, d, sa);
                }
                float a0, a1;
                unpack2(add2(sa, sb), a0, a1);
                S[r] = a0 + a1;
            }

            const float* brow_base = &beta_s[lt * BROW];
            const float* arow = &al_s[lt * 24];

            #pragma unroll
            for (int jp = 0; jp < 12; jp++) {
                // scalar diffs for this j-pair
                float dja[IPT], djb[IPT];
                #pragma unroll
                for (int r = 0; r < IPT; r++) unpack2(df2[r][jp], dja[r], djb[r]);

                #pragma unroll
                for (int h = 0; h < 2; h++) {
                    const int j = 2 * jp + h;
                    const u64* brow = (const u64*)(brow_base + j * 24);
                    // 4 independent FFMA2 chains (2 per i-row)
                    u64 t0a = 0ull, t0b = 0ull, t1a = 0ull, t1b = 0ull;
                    #pragma unroll
                    for (int p = 0; p < 12; p++) {
                        u64 b = brow[p];   // broadcast LDS, 16B-vectorizable pairs
                        if (p & 1) {
                            t0b = ffma2(b, df2[0][p], t0b);
                            t1b = ffma2(b, df2[1][p], t1b);
                        } else {
                            t0a = ffma2(b, df2[0][p], t0a);
                            t1a = ffma2(b, df2[1][p], t1a);
                        }
                    }
                    const float bdiag = brow_base[j * 24 + j];
                    const float aj = arow[j];

                    float lo, hi, tt, dj, w, ej;

                    dj = h ? djb[0] : dja[0];
                    unpack2(add2(t0a, t0b), lo, hi);
                    tt = lo + hi;
                    tt = fmaf(-bdiag, dj, tt);          // drop a==j term
                    w  = fmaf(2.0f, tt, aj);
                    ej = __expf(fmaf(dj, dj, -S[0]));   // arg <= 0, safe
                    acc[0][j] = fmaf(ej, w, acc[0][j]);

                    dj = h ? djb[1] : dja[1];
                    unpack2(add2(t1a, t1b), lo, hi);
                    tt = lo + hi;
                    tt = fmaf(-bdiag, dj, tt);
                    w  = fmaf(2.0f, tt, aj);
                    ej = __expf(fmaf(dj, dj, -S[1]));
                    acc[1][j] = fmaf(ej, w, acc[1][j]);
                }
            }
        }
    }

    // write split-l partials (deterministic reduction in second kernel)
    const size_t base = (size_t)blockIdx.y * NN;
    if (i0 < NN) {
        float4* dst = (float4*)&g_partial[(base + i0) * DD];
        #pragma unroll
        for (int q = 0; q < 6; q++)
            dst[q] = make_float4(acc[0][4*q], acc[0][4*q+1], acc[0][4*q+2], acc[0][4*q+3]);
    }
    if (i1 < NN) {
        float4* dst = (float4*)&g_partial[(base + i1) * DD];
        #pragma unroll
        for (int q = 0; q < 6; q++)
            dst[q] = make_float4(acc[1][4*q], acc[1][4*q+1], acc[1][4*q+2], acc[1][4*q+3]);
    }
}

__global__ void notears_reduce(float* __restrict__ out) {
    int idx = blockIdx.x * blockDim.x + threadIdx.x;
    if (idx < NN * DD) {
        float s = 0.0f;
        #pragma unroll
        for (int p = 0; p < LSPLIT; p++) s += g_partial[(size_t)p * NN * DD + idx];
        out[idx] = s;
    }
}

extern "C" void kernel_launch(void* const* d_in, const int* in_sizes, int n_in,
                              void* d_out, int out_size) {
    const float* x     = (const float*)d_in[0];
    const float* alpha = (const float*)d_in[1];
    const float* beta  = (const float*)d_in[2];

    dim3 grid(NIB, LSPLIT);
    notears_main<<<grid, BLK>>>(x, alpha, beta);
    notears_reduce<<<(NN * DD + 255) / 256, 256>>>((float*)d_out);
}